// round 8
// baseline (speedup 1.0000x reference)
#include <cuda_runtime.h>
#include <cstdint>

// MultiGaussianReadoutLayer fused kernel, R8.
// B=32, O=12000, F_IN=64, F_OUT=4, M=16.
//
// R8 = R7 (warp=o broadcast weight loads, FFMA2 packed math, smem exchange
// for the coalesced eps stage) + occupancy 24 -> 32 warps/SM:
//  - x staged in eighths (FQ=8, 9.2KB tile)
//  - exchange buffer reuses the sigma_w smem region (dead after mainloop)
//  - smem 50.8KB/CTA -> 4 CTAs/SM; __launch_bounds__(256,4) -> <=64 regs

#define B_    32
#define O_    12000
#define FIN   64
#define M_    16
#define OB    8
#define NT    256
#define FQ    8             // f per staged chunk
#define NQ    (FIN / FQ)    // 8
#define XSTR  289           // f-row stride: b*9+o addressing, conflict-free LDS.32
#define EX_BS 164           // exchange b-stride (floats)
#define EX_OS 20            // exchange o-stride (floats)

#define SW_OFF 0
#define MW_OFF (OB * 1024)                       // 8192
#define SB_OFF (MW_OFF + OB * 256)               // 10240
#define MB_OFF (SB_OFF + OB * 16)                // 10368
#define SX_OFF (MB_OFF + OB * 4)                 // 10400
#define SMEM_FLOATS (SX_OFF + FQ * XSTR)         // 12712 floats = 50848 B

__device__ __forceinline__ uint64_t pack2(float lo, float hi) {
    uint64_t r; asm("mov.b64 %0, {%1,%2};" : "=l"(r) : "f"(lo), "f"(hi)); return r;
}
__device__ __forceinline__ uint64_t ffma2(uint64_t a, uint64_t b, uint64_t c) {
    uint64_t d; asm("fma.rn.f32x2 %0, %1, %2, %3;" : "=l"(d) : "l"(a), "l"(b), "l"(c));
    return d;
}
__device__ __forceinline__ void unpack2(uint64_t v, float& lo, float& hi) {
    asm("mov.b64 {%0,%1}, %2;" : "=f"(lo), "=f"(hi) : "l"(v));
}

__global__ void __launch_bounds__(NT, 4)
mgr_kernel(const float* __restrict__ x,
           const float* __restrict__ mu_w,
           const float* __restrict__ mu_b,
           const float* __restrict__ sigma_w,
           const float* __restrict__ sigma_b,
           const float* __restrict__ eps,
           float* __restrict__ out)
{
    extern __shared__ __align__(16) float smem[];
    float* sw = smem + SW_OFF;
    float* mw = smem + MW_OFF;
    float* sb = smem + SB_OFF;
    float* mb = smem + MB_OFF;
    float* sx = smem + SX_OFF;

    const int tid    = threadIdx.x;
    const int o_base = blockIdx.x * OB;

    // ---- stage weights + biases (coalesced float4, linear smem) ----
    {
        const float4* src_s = (const float4*)(sigma_w + (size_t)o_base * 1024);
        #pragma unroll
        for (int i = tid; i < OB * 256; i += NT)
            ((float4*)sw)[i] = src_s[i];
        const float4* src_m = (const float4*)(mu_w + (size_t)o_base * 256);
        #pragma unroll
        for (int i = tid; i < OB * 64; i += NT)
            ((float4*)mw)[i] = src_m[i];
        if (tid < OB * 16) sb[tid] = sigma_b[(size_t)o_base * 16 + tid];
        if (tid < OB * 4)  mb[tid] = mu_b[(size_t)o_base * 4 + tid];
    }

    // mainloop mapping: warp <-> instance, lane <-> batch row
    const int o_w  = tid >> 5;        // 0..7
    const int lane = tid & 31;        // b

    const float* swp = sw + o_w * 1024;
    const float* mwp = mw + o_w * 256;

    uint64_t sacc[8], macc[2];

    #pragma unroll
    for (int q = 0; q < NQ; q++) {
        // ---- stage x chunk transposed: sx[f_local*XSTR + b*9 + o] ----
        // 512 float4 per chunk, 2 per thread, coalesced 32B segments per o
        #pragma unroll
        for (int i = tid; i < B_ * OB * (FQ / 4); i += NT) {
            int bb  = i >> 4;          // 16 float4 per b (8 o x 2 f4)
            int r   = i & 15;
            int o   = r >> 1;
            int f4l = r & 1;
            float4 v = ((const float4*)x)[((size_t)bb * O_ + o_base + o) * 16 + q * 2 + f4l];
            float* dst = sx + (f4l * 4) * XSTR + bb * 9 + o;
            dst[0]        = v.x;
            dst[XSTR]     = v.y;
            dst[2 * XSTR] = v.z;
            dst[3 * XSTR] = v.w;
        }
        __syncthreads();

        if (q == 0) {  // biases visible after first sync
            #pragma unroll
            for (int j = 0; j < 8; j++)
                sacc[j] = pack2(sb[o_w * 16 + 2 * j], sb[o_w * 16 + 2 * j + 1]);
            macc[0] = pack2(mb[o_w * 4 + 0], mb[o_w * 4 + 1]);
            macc[1] = pack2(mb[o_w * 4 + 2], mb[o_w * 4 + 3]);
        }

        #pragma unroll
        for (int fl = 0; fl < FQ; fl++) {
            const int f = q * FQ + fl;
            const float xf = sx[fl * XSTR + lane * 9 + o_w];   // conflict-free LDS.32
            const uint64_t xx = pack2(xf, xf);

            // warp-uniform addresses -> broadcast, 1 wavefront each
            ulonglong2 m2 = *(const ulonglong2*)(mwp + f * 4);
            macc[0] = ffma2(m2.x, xx, macc[0]);
            macc[1] = ffma2(m2.y, xx, macc[1]);

            #pragma unroll
            for (int h = 0; h < 2; h++) {
                ulonglong2 sA = *(const ulonglong2*)(swp + f * 16 + h * 8);
                ulonglong2 sB = *(const ulonglong2*)(swp + f * 16 + h * 8 + 4);
                sacc[4 * h + 0] = ffma2(sA.x, xx, sacc[4 * h + 0]);
                sacc[4 * h + 1] = ffma2(sA.y, xx, sacc[4 * h + 1]);
                sacc[4 * h + 2] = ffma2(sB.x, xx, sacc[4 * h + 2]);
                sacc[4 * h + 3] = ffma2(sB.y, xx, sacc[4 * h + 3]);
            }
        }
        __syncthreads();
    }

    // ---- exchange sig/mu through smem (reuse dead sigma_w region) ----
    {
        float* exw = sw + lane * EX_BS + o_w * EX_OS;
        *(ulonglong2*)(exw +  0) = make_ulonglong2(sacc[0], sacc[1]);
        *(ulonglong2*)(exw +  4) = make_ulonglong2(sacc[2], sacc[3]);
        *(ulonglong2*)(exw +  8) = make_ulonglong2(sacc[4], sacc[5]);
        *(ulonglong2*)(exw + 12) = make_ulonglong2(sacc[6], sacc[7]);
        *(ulonglong2*)(exw + 16) = make_ulonglong2(macc[0], macc[1]);
    }
    __syncthreads();

    const int o_l = tid & (OB - 1);
    const int b   = tid >> 3;
    const int og  = o_base + o_l;

    float sig[16], mu0, mu1, mu2, mu3;
    {
        const float* exr = sw + b * EX_BS + o_l * EX_OS;
        #pragma unroll
        for (int j = 0; j < 8; j++) {
            uint64_t v = ((const uint64_t*)exr)[j];
            unpack2(v, sig[2 * j], sig[2 * j + 1]);
        }
        uint64_t v0 = ((const uint64_t*)exr)[8];
        uint64_t v1 = ((const uint64_t*)exr)[9];
        unpack2(v0, mu0, mu1);
        unpack2(v1, mu2, mu3);
    }

    uint64_t ep01[4], ep23[4];
    #pragma unroll
    for (int f = 0; f < 4; f++) {
        ep01[f] = pack2(sig[f],     sig[4 + f]);
        ep23[f] = pack2(sig[8 + f], sig[12 + f]);
    }
    const uint64_t mu01 = pack2(mu0, mu1);
    const uint64_t mu23 = pack2(mu2, mu3);

    // ---- eps application: [M, B, O, 4] float4 coalesced ----
    const size_t beo = (size_t)b * O_ + og;
    #pragma unroll
    for (int m = 0; m < M_; m++) {
        const size_t idx = ((size_t)m * B_ * O_ + beo) * 4;
        float4 e = __ldg((const float4*)(eps + idx));
        uint64_t ex = pack2(e.x, e.x), ey = pack2(e.y, e.y);
        uint64_t ez = pack2(e.z, e.z), ew = pack2(e.w, e.w);

        uint64_t p01 = ffma2(ep01[0], ex, mu01);
        p01 = ffma2(ep01[1], ey, p01);
        p01 = ffma2(ep01[2], ez, p01);
        p01 = ffma2(ep01[3], ew, p01);

        uint64_t p23 = ffma2(ep23[0], ex, mu23);
        p23 = ffma2(ep23[1], ey, p23);
        p23 = ffma2(ep23[2], ez, p23);
        p23 = ffma2(ep23[3], ew, p23);

        float4 r;
        unpack2(p01, r.x, r.y);
        unpack2(p23, r.z, r.w);
        *(float4*)(out + idx) = r;
    }
}

extern "C" void kernel_launch(void* const* d_in, const int* in_sizes, int n_in,
                              void* d_out, int out_size)
{
    const float* x       = (const float*)d_in[0];
    const float* mu_w    = (const float*)d_in[1];
    const float* mu_b    = (const float*)d_in[2];
    const float* sigma_w = (const float*)d_in[3];
    const float* sigma_b = (const float*)d_in[4];
    const float* eps     = (const float*)d_in[5];
    float* out           = (float*)d_out;

    const int smem_bytes = SMEM_FLOATS * sizeof(float);   // 50848
    cudaFuncSetAttribute(mgr_kernel,
                         cudaFuncAttributeMaxDynamicSharedMemorySize, smem_bytes);

    dim3 grid(O_ / OB);   // 1500 CTAs
    dim3 block(NT);
    mgr_kernel<<<grid, block, smem_bytes>>>(x, mu_w, mu_b, sigma_w, sigma_b, eps, out);
}

// round 10
// speedup vs baseline: 1.2027x; 1.2027x over previous
#include <cuda_runtime.h>
#include <cstdint>

// MultiGaussianReadoutLayer fused kernel, R9.
// B=32, O=12000, F_IN=64, F_OUT=4, M=16.
//
// R9 = R7 (warp=o broadcast weight LDS, FFMA2 packed math, smem exchange,
// 3 CTAs/SM) + DOUBLE-BUFFERED x staging (FQ=8, 2 buffers):
// chunk q+1's LDG/STS issue before chunk q's compute, one sync per chunk.
// Removes the sync-exposed DRAM latency that bound R7/R8.

#define B_    32
#define O_    12000
#define FIN   64
#define M_    16
#define OB    8
#define NT    256
#define FQ    8             // f per staged chunk
#define NQ    (FIN / FQ)    // 8
#define XSTR  289           // f-row stride: b*9+o addressing, conflict-free LDS.32
#define XBUF  (FQ * XSTR)   // 2312 floats per buffer
#define EX_BS 164           // exchange b-stride (floats)
#define EX_OS 20            // exchange o-stride (floats)

#define SW_OFF 0
#define MW_OFF (OB * 1024)                       // 8192
#define SB_OFF (MW_OFF + OB * 256)               // 10240
#define MB_OFF (SB_OFF + OB * 16)                // 10368
#define SX_OFF (MB_OFF + OB * 4)                 // 10400
#define SMEM_FLOATS (SX_OFF + 2 * XBUF)          // 15024 floats = 60096 B

__device__ __forceinline__ uint64_t pack2(float lo, float hi) {
    uint64_t r; asm("mov.b64 %0, {%1,%2};" : "=l"(r) : "f"(lo), "f"(hi)); return r;
}
__device__ __forceinline__ uint64_t ffma2(uint64_t a, uint64_t b, uint64_t c) {
    uint64_t d; asm("fma.rn.f32x2 %0, %1, %2, %3;" : "=l"(d) : "l"(a), "l"(b), "l"(c));
    return d;
}
__device__ __forceinline__ void unpack2(uint64_t v, float& lo, float& hi) {
    asm("mov.b64 {%0,%1}, %2;" : "=f"(lo), "=f"(hi) : "l"(v));
}

__global__ void __launch_bounds__(NT, 3)
mgr_kernel(const float* __restrict__ x,
           const float* __restrict__ mu_w,
           const float* __restrict__ mu_b,
           const float* __restrict__ sigma_w,
           const float* __restrict__ sigma_b,
           const float* __restrict__ eps,
           float* __restrict__ out)
{
    extern __shared__ __align__(16) float smem[];
    float* sw = smem + SW_OFF;
    float* mw = smem + MW_OFF;
    float* sb = smem + SB_OFF;
    float* mb = smem + MB_OFF;
    float* sx = smem + SX_OFF;

    const int tid    = threadIdx.x;
    const int o_base = blockIdx.x * OB;

    // staging decomposition for x chunks (2 float4 per thread per chunk)
    const int st_bb  = tid >> 4;        // 0..15  -> handles b = st_bb (i<256) / st_bb+16
    const int st_r   = tid & 15;
    const int st_o   = st_r >> 1;
    const int st_f4l = st_r & 1;
    const float4* xg = (const float4*)x;

    // ---- stage weights + biases (coalesced float4, linear smem) ----
    {
        const float4* src_s = (const float4*)(sigma_w + (size_t)o_base * 1024);
        #pragma unroll
        for (int i = tid; i < OB * 256; i += NT)
            ((float4*)sw)[i] = src_s[i];
        const float4* src_m = (const float4*)(mu_w + (size_t)o_base * 256);
        #pragma unroll
        for (int i = tid; i < OB * 64; i += NT)
            ((float4*)mw)[i] = src_m[i];
        if (tid < OB * 16) sb[tid] = sigma_b[(size_t)o_base * 16 + tid];
        if (tid < OB * 4)  mb[tid] = mu_b[(size_t)o_base * 4 + tid];
    }

    // ---- stage chunk 0 into buffer 0 ----
    {
        #pragma unroll
        for (int h = 0; h < 2; h++) {
            int bb = st_bb + h * 16;
            float4 v = xg[((size_t)bb * O_ + o_base + st_o) * 16 + st_f4l];
            float* dst = sx + (st_f4l * 4) * XSTR + bb * 9 + st_o;
            dst[0]        = v.x;
            dst[XSTR]     = v.y;
            dst[2 * XSTR] = v.z;
            dst[3 * XSTR] = v.w;
        }
    }
    __syncthreads();

    // mainloop mapping: warp <-> instance, lane <-> batch row
    const int o_w  = tid >> 5;
    const int lane = tid & 31;

    const float* swp = sw + o_w * 1024;
    const float* mwp = mw + o_w * 256;

    uint64_t sacc[8], macc[2];
    #pragma unroll
    for (int j = 0; j < 8; j++)
        sacc[j] = pack2(sb[o_w * 16 + 2 * j], sb[o_w * 16 + 2 * j + 1]);
    macc[0] = pack2(mb[o_w * 4 + 0], mb[o_w * 4 + 1]);
    macc[1] = pack2(mb[o_w * 4 + 2], mb[o_w * 4 + 3]);

    // ---- double-buffered mainloop ----
    #pragma unroll
    for (int q = 0; q < NQ; q++) {
        const float* cur = sx + (q & 1) * XBUF;
        float*       nxt = sx + ((q + 1) & 1) * XBUF;

        // prefetch chunk q+1 (LDG overlaps compute below)
        if (q < NQ - 1) {
            #pragma unroll
            for (int h = 0; h < 2; h++) {
                int bb = st_bb + h * 16;
                float4 v = xg[((size_t)bb * O_ + o_base + st_o) * 16 + (q + 1) * 2 + st_f4l];
                float* dst = nxt + (st_f4l * 4) * XSTR + bb * 9 + st_o;
                dst[0]        = v.x;
                dst[XSTR]     = v.y;
                dst[2 * XSTR] = v.z;
                dst[3 * XSTR] = v.w;
            }
        }

        // compute chunk q
        #pragma unroll
        for (int fl = 0; fl < FQ; fl++) {
            const int f = q * FQ + fl;
            const float xf = cur[fl * XSTR + lane * 9 + o_w];   // conflict-free LDS.32
            const uint64_t xx = pack2(xf, xf);

            // warp-uniform addresses -> broadcast, 1 wavefront each
            ulonglong2 m2 = *(const ulonglong2*)(mwp + f * 4);
            macc[0] = ffma2(m2.x, xx, macc[0]);
            macc[1] = ffma2(m2.y, xx, macc[1]);

            #pragma unroll
            for (int h = 0; h < 2; h++) {
                ulonglong2 sA = *(const ulonglong2*)(swp + f * 16 + h * 8);
                ulonglong2 sB = *(const ulonglong2*)(swp + f * 16 + h * 8 + 4);
                sacc[4 * h + 0] = ffma2(sA.x, xx, sacc[4 * h + 0]);
                sacc[4 * h + 1] = ffma2(sA.y, xx, sacc[4 * h + 1]);
                sacc[4 * h + 2] = ffma2(sB.x, xx, sacc[4 * h + 2]);
                sacc[4 * h + 3] = ffma2(sB.y, xx, sacc[4 * h + 3]);
            }
        }
        __syncthreads();
    }

    // ---- exchange sig/mu through smem (reuse dead sigma_w region) ----
    {
        float* exw = sw + lane * EX_BS + o_w * EX_OS;
        *(ulonglong2*)(exw +  0) = make_ulonglong2(sacc[0], sacc[1]);
        *(ulonglong2*)(exw +  4) = make_ulonglong2(sacc[2], sacc[3]);
        *(ulonglong2*)(exw +  8) = make_ulonglong2(sacc[4], sacc[5]);
        *(ulonglong2*)(exw + 12) = make_ulonglong2(sacc[6], sacc[7]);
        *(ulonglong2*)(exw + 16) = make_ulonglong2(macc[0], macc[1]);
    }
    __syncthreads();

    const int o_l = tid & (OB - 1);
    const int b   = tid >> 3;
    const int og  = o_base + o_l;

    float sig[16], mu0, mu1, mu2, mu3;
    {
        const float* exr = sw + b * EX_BS + o_l * EX_OS;
        #pragma unroll
        for (int j = 0; j < 8; j++) {
            uint64_t v = ((const uint64_t*)exr)[j];
            unpack2(v, sig[2 * j], sig[2 * j + 1]);
        }
        uint64_t v0 = ((const uint64_t*)exr)[8];
        uint64_t v1 = ((const uint64_t*)exr)[9];
        unpack2(v0, mu0, mu1);
        unpack2(v1, mu2, mu3);
    }

    uint64_t ep01[4], ep23[4];
    #pragma unroll
    for (int f = 0; f < 4; f++) {
        ep01[f] = pack2(sig[f],     sig[4 + f]);
        ep23[f] = pack2(sig[8 + f], sig[12 + f]);
    }
    const uint64_t mu01 = pack2(mu0, mu1);
    const uint64_t mu23 = pack2(mu2, mu3);

    // ---- eps application: [M, B, O, 4] float4 coalesced ----
    const size_t beo = (size_t)b * O_ + og;
    #pragma unroll
    for (int m = 0; m < M_; m++) {
        const size_t idx = ((size_t)m * B_ * O_ + beo) * 4;
        float4 e = __ldg((const float4*)(eps + idx));
        uint64_t ex = pack2(e.x, e.x), ey = pack2(e.y, e.y);
        uint64_t ez = pack2(e.z, e.z), ew = pack2(e.w, e.w);

        uint64_t p01 = ffma2(ep01[0], ex, mu01);
        p01 = ffma2(ep01[1], ey, p01);
        p01 = ffma2(ep01[2], ez, p01);
        p01 = ffma2(ep01[3], ew, p01);

        uint64_t p23 = ffma2(ep23[0], ex, mu23);
        p23 = ffma2(ep23[1], ey, p23);
        p23 = ffma2(ep23[2], ez, p23);
        p23 = ffma2(ep23[3], ew, p23);

        float4 r;
        unpack2(p01, r.x, r.y);
        unpack2(p23, r.z, r.w);
        *(float4*)(out + idx) = r;
    }
}

extern "C" void kernel_launch(void* const* d_in, const int* in_sizes, int n_in,
                              void* d_out, int out_size)
{
    const float* x       = (const float*)d_in[0];
    const float* mu_w    = (const float*)d_in[1];
    const float* mu_b    = (const float*)d_in[2];
    const float* sigma_w = (const float*)d_in[3];
    const float* sigma_b = (const float*)d_in[4];
    const float* eps     = (const float*)d_in[5];
    float* out           = (float*)d_out;

    const int smem_bytes = SMEM_FLOATS * sizeof(float);   // 60096
    cudaFuncSetAttribute(mgr_kernel,
                         cudaFuncAttributeMaxDynamicSharedMemorySize, smem_bytes);

    dim3 grid(O_ / OB);   // 1500 CTAs
    dim3 block(NT);
    mgr_kernel<<<grid, block, smem_bytes>>>(x, mu_w, mu_b, sigma_w, sigma_b, eps, out);
}

// round 12
// speedup vs baseline: 1.4255x; 1.1852x over previous
#include <cuda_runtime.h>
#include <cstdint>

// MultiGaussianReadoutLayer fused kernel, R11.
// B=32, O=12000, F_IN=64, F_OUT=4, M=16.
//
// R11 = R10 (half-warp output split: lane=(half,b-pair), weight LDS traffic
// 21 -> 12 wavefronts/warp/f) with the R10 RACE FIXED: accumulator init from
// sb/mb moved after the first __syncthreads() (q==0 branch), as in R7/R9.

#define B_    32
#define O_    12000
#define FIN   64
#define M_    16
#define OB    8
#define NT    256
#define FQ    16            // f per staged chunk (4 chunks, 4 syncs)
#define NQ    (FIN / FQ)    // 4
#define XSTR  289           // f-row stride: b*9+o addressing, conflict-free LDS.32
#define EX_BS 164           // exchange b-stride (floats), 8B-aligned
#define EX_OS 20            // exchange o-stride (floats)

#define SW_OFF 0
#define MW_OFF (OB * 1024)                       // 8192
#define SB_OFF (MW_OFF + OB * 256)               // 10240
#define MB_OFF (SB_OFF + OB * 16)                // 10368
#define SX_OFF (MB_OFF + OB * 4)                 // 10400
#define SMEM_FLOATS (SX_OFF + FQ * XSTR)         // 15024 floats = 60096 B

__device__ __forceinline__ uint64_t pack2(float lo, float hi) {
    uint64_t r; asm("mov.b64 %0, {%1,%2};" : "=l"(r) : "f"(lo), "f"(hi)); return r;
}
__device__ __forceinline__ uint64_t ffma2(uint64_t a, uint64_t b, uint64_t c) {
    uint64_t d; asm("fma.rn.f32x2 %0, %1, %2, %3;" : "=l"(d) : "l"(a), "l"(b), "l"(c));
    return d;
}
__device__ __forceinline__ void unpack2(uint64_t v, float& lo, float& hi) {
    asm("mov.b64 {%0,%1}, %2;" : "=f"(lo), "=f"(hi) : "l"(v));
}

__global__ void __launch_bounds__(NT, 3)
mgr_kernel(const float* __restrict__ x,
           const float* __restrict__ mu_w,
           const float* __restrict__ mu_b,
           const float* __restrict__ sigma_w,
           const float* __restrict__ sigma_b,
           const float* __restrict__ eps,
           float* __restrict__ out)
{
    extern __shared__ __align__(16) float smem[];
    float* sw = smem + SW_OFF;
    float* mw = smem + MW_OFF;
    float* sb = smem + SB_OFF;
    float* mb = smem + MB_OFF;
    float* sx = smem + SX_OFF;

    const int tid    = threadIdx.x;
    const int o_base = blockIdx.x * OB;

    // ---- stage weights + biases (coalesced float4, linear smem) ----
    {
        const float4* src_s = (const float4*)(sigma_w + (size_t)o_base * 1024);
        #pragma unroll
        for (int i = tid; i < OB * 256; i += NT)
            ((float4*)sw)[i] = src_s[i];
        const float4* src_m = (const float4*)(mu_w + (size_t)o_base * 256);
        #pragma unroll
        for (int i = tid; i < OB * 64; i += NT)
            ((float4*)mw)[i] = src_m[i];
        if (tid < OB * 16) sb[tid] = sigma_b[(size_t)o_base * 16 + tid];
        if (tid < OB * 4)  mb[tid] = mu_b[(size_t)o_base * 4 + tid];
    }

    // mainloop mapping: warp <-> instance; lane = (output-half, b-pair)
    const int o_w  = tid >> 5;         // 0..7
    const int lane = tid & 31;
    const int half = lane >> 4;        // 0: sig[0..7]+mu[0,1]; 1: sig[8..15]+mu[2,3]
    const int bp   = lane & 15;        // covers b = bp and b = bp+16

    const float* swp = sw + o_w * 1024 + half * 8;   // this half's 8 sig weights per f
    const float* mwp = mw + o_w * 256 + half * 2;    // this half's 2 mu weights per f

    // accumulators: 2 b-rows x (4 packed sig-half + 1 packed mu-half)
    uint64_t s0[4], s1[4], m0, m1;

    // ---- mainloop: 4 staged chunks of FQ=16 f-values ----
    #pragma unroll
    for (int q = 0; q < NQ; q++) {
        // stage x chunk transposed: sx[f_local*XSTR + b*9 + o], coalesced LDG
        #pragma unroll
        for (int i = tid; i < B_ * OB * (FQ / 4); i += NT) {   // 1024 float4
            int bb  = i >> 5;
            int r   = i & 31;
            int o   = r >> 2;
            int f4l = r & 3;
            float4 v = ((const float4*)x)[((size_t)bb * O_ + o_base + o) * 16 + q * 4 + f4l];
            float* dst = sx + (f4l * 4) * XSTR + bb * 9 + o;
            dst[0]        = v.x;
            dst[XSTR]     = v.y;
            dst[2 * XSTR] = v.z;
            dst[3 * XSTR] = v.w;
        }
        __syncthreads();

        if (q == 0) {   // init AFTER the first sync: sb/mb now visible (R10 bug fix)
            #pragma unroll
            for (int j = 0; j < 4; j++) {
                uint64_t v = pack2(sb[o_w * 16 + half * 8 + 2 * j],
                                   sb[o_w * 16 + half * 8 + 2 * j + 1]);
                s0[j] = v; s1[j] = v;
            }
            m0 = pack2(mb[o_w * 4 + 2 * half], mb[o_w * 4 + 2 * half + 1]);
            m1 = m0;
        }

        #pragma unroll
        for (int fl = 0; fl < FQ; fl++) {
            const int f = q * FQ + fl;
            // x for both b rows (conflict-free LDS.32)
            const float xa = sx[fl * XSTR + bp * 9 + o_w];
            const float xc = sx[fl * XSTR + (bp + 16) * 9 + o_w];
            const uint64_t xx0 = pack2(xa, xa);
            const uint64_t xx1 = pack2(xc, xc);

            // this half's weights: 8 sig floats + 2 mu floats, shared by both b
            ulonglong2 sA = *(const ulonglong2*)(swp + f * 16);      // sig h*8+0..3
            ulonglong2 sB = *(const ulonglong2*)(swp + f * 16 + 4);  // sig h*8+4..7
            uint64_t   mm = *(const uint64_t*)(mwp + f * 4);         // mu 2h,2h+1

            s0[0] = ffma2(sA.x, xx0, s0[0]);
            s0[1] = ffma2(sA.y, xx0, s0[1]);
            s0[2] = ffma2(sB.x, xx0, s0[2]);
            s0[3] = ffma2(sB.y, xx0, s0[3]);
            m0    = ffma2(mm,   xx0, m0);

            s1[0] = ffma2(sA.x, xx1, s1[0]);
            s1[1] = ffma2(sA.y, xx1, s1[1]);
            s1[2] = ffma2(sB.x, xx1, s1[2]);
            s1[3] = ffma2(sB.y, xx1, s1[3]);
            m1    = ffma2(mm,   xx1, m1);
        }
        __syncthreads();
    }

    // ---- exchange sig/mu through smem (reuse dead sigma_w region) ----
    // slot layout per (b,o): uint64[0..7] = sig pairs, [8] = mu01, [9] = mu23
    // half h writes sig slots h*4..h*4+3 and mu slot 8+h.
    {
        uint64_t* ex0 = (uint64_t*)(sw + bp * EX_BS + o_w * EX_OS);
        uint64_t* ex1 = (uint64_t*)(sw + (bp + 16) * EX_BS + o_w * EX_OS);
        #pragma unroll
        for (int j = 0; j < 4; j++) {
            ex0[half * 4 + j] = s0[j];
            ex1[half * 4 + j] = s1[j];
        }
        ex0[8 + half] = m0;
        ex1[8 + half] = m1;
    }
    __syncthreads();

    const int o_l = tid & (OB - 1);
    const int b   = tid >> 3;
    const int og  = o_base + o_l;

    float sig[16], mu0, mu1, mu2, mu3;
    {
        const uint64_t* exr = (const uint64_t*)(sw + b * EX_BS + o_l * EX_OS);
        #pragma unroll
        for (int j = 0; j < 8; j++)
            unpack2(exr[j], sig[2 * j], sig[2 * j + 1]);
        unpack2(exr[8], mu0, mu1);
        unpack2(exr[9], mu2, mu3);
    }

    uint64_t ep01[4], ep23[4];
    #pragma unroll
    for (int f = 0; f < 4; f++) {
        ep01[f] = pack2(sig[f],     sig[4 + f]);
        ep23[f] = pack2(sig[8 + f], sig[12 + f]);
    }
    const uint64_t mu01 = pack2(mu0, mu1);
    const uint64_t mu23 = pack2(mu2, mu3);

    // ---- eps application: [M, B, O, 4] float4 coalesced ----
    const size_t beo = (size_t)b * O_ + og;
    #pragma unroll
    for (int m = 0; m < M_; m++) {
        const size_t idx = ((size_t)m * B_ * O_ + beo) * 4;
        float4 e = __ldg((const float4*)(eps + idx));
        uint64_t ex = pack2(e.x, e.x), ey = pack2(e.y, e.y);
        uint64_t ez = pack2(e.z, e.z), ew = pack2(e.w, e.w);

        uint64_t p01 = ffma2(ep01[0], ex, mu01);
        p01 = ffma2(ep01[1], ey, p01);
        p01 = ffma2(ep01[2], ez, p01);
        p01 = ffma2(ep01[3], ew, p01);

        uint64_t p23 = ffma2(ep23[0], ex, mu23);
        p23 = ffma2(ep23[1], ey, p23);
        p23 = ffma2(ep23[2], ez, p23);
        p23 = ffma2(ep23[3], ew, p23);

        float4 r;
        unpack2(p01, r.x, r.y);
        unpack2(p23, r.z, r.w);
        *(float4*)(out + idx) = r;
    }
}

extern "C" void kernel_launch(void* const* d_in, const int* in_sizes, int n_in,
                              void* d_out, int out_size)
{
    const float* x       = (const float*)d_in[0];
    const float* mu_w    = (const float*)d_in[1];
    const float* mu_b    = (const float*)d_in[2];
    const float* sigma_w = (const float*)d_in[3];
    const float* sigma_b = (const float*)d_in[4];
    const float* eps     = (const float*)d_in[5];
    float* out           = (float*)d_out;

    const int smem_bytes = SMEM_FLOATS * sizeof(float);   // 60096
    cudaFuncSetAttribute(mgr_kernel,
                         cudaFuncAttributeMaxDynamicSharedMemorySize, smem_bytes);

    dim3 grid(O_ / OB);   // 1500 CTAs
    dim3 block(NT);
    mgr_kernel<<<grid, block, smem_bytes>>>(x, mu_w, mu_b, sigma_w, sigma_b, eps, out);
}